// round 10
// baseline (speedup 1.0000x reference)
#include <cuda_runtime.h>
#include <cuda_bf16.h>

static constexpr int BS = 32;
static constexpr int S  = 2048;
static constexpr int H  = 1024;

// Scratch for v[b,h] = hidden[b] @ W  (device global: no allocs allowed).
// Zeroed each launch via a captured cudaMemsetAsync node.
__device__ float g_v[BS * H];

// ---------------------------------------------------------------------------
// Stage 1: v[b,h] = sum_k hidden[b,k] * W[k,h]
// grid: (H/128, BS/16, K/64) = (8, 2, 16) = 256 blocks, 128 threads.
// Each thread owns one h column, SIXTEEN batches, 64 k values. Each W load
// feeds 16 FMAs (vs 8 before): W L2 traffic halves to 8 MB, per-thread FMA
// work doubles to 1024 — enough issue-work to hide L2 load latency at
// ~7 warps/SM. k-chunks reduce via atomicAdd (spread addresses).
// PDL trigger early so the scores grid pre-launches and parks.
// ---------------------------------------------------------------------------
__global__ void __launch_bounds__(128) v_kernel(const float* __restrict__ hidden,
                                                const float* __restrict__ W) {
    cudaTriggerProgrammaticLaunchCompletion();

    __shared__ float sh[16][64];
    const int h  = blockIdx.x * 128 + threadIdx.x;
    const int b0 = blockIdx.y * 16;
    const int k0 = blockIdx.z * 64;

#pragma unroll
    for (int i = threadIdx.x; i < 16 * 64; i += 128) {
        int bb = i >> 6, kk = i & 63;
        sh[bb][kk] = hidden[(b0 + bb) * H + (k0 + kk)];
    }
    __syncthreads();

    float acc[16];
#pragma unroll
    for (int bb = 0; bb < 16; bb++) acc[bb] = 0.0f;

#pragma unroll 8
    for (int kk = 0; kk < 64; kk++) {
        float w = W[(size_t)(k0 + kk) * H + h];   // coalesced across threads (h)
#pragma unroll
        for (int bb = 0; bb < 16; bb++)
            acc[bb] = fmaf(sh[bb][kk], w, acc[bb]);  // smem broadcast
    }

#pragma unroll
    for (int bb = 0; bb < 16; bb++)
        atomicAdd(&g_v[(b0 + bb) * H + h], acc[bb]);
}

// ---------------------------------------------------------------------------
// Stage 2: scores[b,s] = dot(enc[b,s,:], v[b,:])   -- the HBM-bound stage.
// Proven shape: 256-thread blocks, one warp per (b,s), 8 rows/block,
// v[b] staged in 4 KB smem, enc via __ldcs (268 MB single-use, streaming),
// 8 LDG.128 in flight per lane. ~82% of HBM spec achieved.
// PDL: blocks may start during v_kernel, so gridDependencySynchronize()
// before reading g_v; triggers own completion so softmax pre-launches.
// ---------------------------------------------------------------------------
__global__ void __launch_bounds__(256) scores_kernel(const float* __restrict__ enc,
                                                     float* __restrict__ out) {
    __shared__ float4 shv[H / 4];  // 4 KB: v[b]
    const int warp = threadIdx.x >> 5;
    const int lane = threadIdx.x & 31;
    const int b = blockIdx.x >> 8;                  // 256 blocks per batch
    const int s = ((blockIdx.x & 255) << 3) + warp; // 8 rows per block

    cudaGridDependencySynchronize();                // wait: g_v complete
    cudaTriggerProgrammaticLaunchCompletion();      // allow softmax pre-launch

    const float4* vg = (const float4*)(g_v + b * H);
    for (int i = threadIdx.x; i < H / 4; i += 256) shv[i] = vg[i];
    __syncthreads();

    const float4* e = (const float4*)(enc + ((size_t)b * S + s) * H);

    float a0 = 0.f, a1 = 0.f;
#pragma unroll
    for (int i = 0; i < 8; i++) {
        float4 x = __ldcs(e + lane + 32 * i);
        float4 v = shv[lane + 32 * i];
        a0 = fmaf(x.x, v.x, a0);
        a1 = fmaf(x.y, v.y, a1);
        a0 = fmaf(x.z, v.z, a0);
        a1 = fmaf(x.w, v.w, a1);
    }
    float acc = a0 + a1;
#pragma unroll
    for (int off = 16; off; off >>= 1)
        acc += __shfl_xor_sync(0xffffffffu, acc, off);
    if (lane == 0) out[b * S + s] = acc;
}

// ---------------------------------------------------------------------------
// Stage 3: in-place row softmax over S=2048. One block per batch row
// (proven 32x256 shape). PDL: blocks pre-launch during scores' tail, park at
// gridDependencySynchronize, then run with zero launch-ramp cost.
// (Bias term c[b] is constant over s -> cancels in softmax; never computed.)
// ---------------------------------------------------------------------------
__global__ void __launch_bounds__(256) softmax_kernel(float* __restrict__ out) {
    const int b    = blockIdx.x;
    const int tid  = threadIdx.x;
    const int warp = tid >> 5, lane = tid & 31;
    float* row = out + b * S;
    __shared__ float red[8];

    cudaGridDependencySynchronize();                // wait: scores complete

    float v[8];
    float m = -1e30f;
#pragma unroll
    for (int i = 0; i < 8; i++) {
        v[i] = row[tid + 256 * i];
        m = fmaxf(m, v[i]);
    }
#pragma unroll
    for (int off = 16; off; off >>= 1)
        m = fmaxf(m, __shfl_xor_sync(0xffffffffu, m, off));
    if (lane == 0) red[warp] = m;
    __syncthreads();
    float M = red[0];
#pragma unroll
    for (int w = 1; w < 8; w++) M = fmaxf(M, red[w]);

    float sum = 0.f;
#pragma unroll
    for (int i = 0; i < 8; i++) {
        v[i] = __expf(v[i] - M);
        sum += v[i];
    }
#pragma unroll
    for (int off = 16; off; off >>= 1)
        sum += __shfl_xor_sync(0xffffffffu, sum, off);
    __syncthreads();               // red[] reuse hazard
    if (lane == 0) red[warp] = sum;
    __syncthreads();
    float T = 0.f;
#pragma unroll
    for (int w = 0; w < 8; w++) T += red[w];
    float inv = 1.0f / T;
#pragma unroll
    for (int i = 0; i < 8; i++)
        row[tid + 256 * i] = v[i] * inv;
}

// ---------------------------------------------------------------------------
extern "C" void kernel_launch(void* const* d_in, const int* in_sizes, int n_in,
                              void* d_out, int out_size) {
    // Identify inputs by element count (all four sizes are distinct).
    const float* hidden = nullptr;  // 32768
    const float* enc    = nullptr;  // 67108864
    const float* W      = nullptr;  // 1048576
    for (int i = 0; i < n_in; i++) {
        long sz = in_sizes[i];
        if      (sz == (long)BS * S * H) enc    = (const float*)d_in[i];
        else if (sz == (long)H * H)      W      = (const float*)d_in[i];
        else if (sz == (long)BS * H)     hidden = (const float*)d_in[i];
        // bias (H) intentionally unused: softmax-invariant per-row constant
    }
    float* out = (float*)d_out;  // [BS, S] fp32

    // Stage 0: zero g_v via a captured memset node (no kernel launch).
    void* vptr = nullptr;
    cudaGetSymbolAddress(&vptr, g_v);
    cudaMemsetAsync(vptr, 0, sizeof(float) * BS * H, 0);

    // Stage 1: plain launch (full dependency on the memset node).
    v_kernel<<<dim3(H / 128, BS / 16, 16), 128>>>(hidden, W);

    // Stages 2+3: PDL launches — overlap each kernel's launch/ramp with the
    // predecessor's execution; device-side gridDependencySynchronize provides
    // the data-ordering barrier.
    cudaLaunchAttribute attrs[1];
    attrs[0].id = cudaLaunchAttributeProgrammaticStreamSerialization;
    attrs[0].val.programmaticStreamSerializationAllowed = 1;

    {
        cudaLaunchConfig_t cfg = {};
        cfg.gridDim  = dim3((BS * S) / 8);
        cfg.blockDim = dim3(256);
        cfg.stream   = 0;
        cfg.attrs    = attrs;
        cfg.numAttrs = 1;
        cudaLaunchKernelEx(&cfg, scores_kernel, enc, out);
    }
    {
        cudaLaunchConfig_t cfg = {};
        cfg.gridDim  = dim3(BS);
        cfg.blockDim = dim3(256);
        cfg.stream   = 0;
        cfg.attrs    = attrs;
        cfg.numAttrs = 1;
        cudaLaunchKernelEx(&cfg, softmax_kernel, out);
    }
}